// round 13
// baseline (speedup 1.0000x reference)
#include <cuda_runtime.h>
#include <math.h>

#define N_IMG   65536
#define IMG_D   2048
#define N_CLS   2048
#define ATT_D   1024
#define HC      512
#define TSOFT   10.0f
#define THRESH  0.17364817766693041f
#define MAXSEL  128

// ---------------- scratch (static device memory; no allocation) ----------------
__device__ float g_a1[N_CLS * HC];
__device__ float g_a2[N_CLS * HC];
__device__ float g_b2[N_CLS * HC];
__device__ float g_d[N_CLS * N_CLS];
__device__ float g_rnorm[N_CLS];
__device__ float g_protos[N_CLS * IMG_D];
__device__ float g_attr_tf[N_CLS * ATT_D];
__device__ float g_ga_tf[ATT_D * HC];
__device__ float g_gv_tf[ATT_D * HC];
__device__ int   g_count[N_CLS];
__device__ int   g_offset[N_CLS];
__device__ int   g_cursor[N_CLS];
__device__ int   g_perm[N_IMG];
__device__ int   g_sel_cnt[N_CLS];
__device__ int   g_sel_idx[N_CLS * MAXSEL];
__device__ float g_sel_w[N_CLS * MAXSEL];

__device__ __forceinline__ float f2tf(float x) {
    unsigned r;
    asm("cvt.rna.tf32.f32 %0, %1;" : "=r"(r) : "f"(x));
    return __uint_as_float(r);
}

// round attr+ga+gv to tf32 in one launch (flat float4 index)
#define A4  (N_CLS * ATT_D / 4)
#define G4  (ATT_D * HC / 4)
__global__ void round_all_kernel(const float* __restrict__ attr, const float* __restrict__ ga,
                                 const float* __restrict__ gv) {
    int i = blockIdx.x * blockDim.x + threadIdx.x;
    const float4* src;
    float4* dst;
    int j;
    if (i < A4)            { src = (const float4*)attr; dst = (float4*)g_attr_tf; j = i; }
    else if (i < A4 + G4)  { src = (const float4*)ga;   dst = (float4*)g_ga_tf;   j = i - A4; }
    else if (i < A4 + 2*G4){ src = (const float4*)gv;   dst = (float4*)g_gv_tf;   j = i - A4 - G4; }
    else return;
    float4 v = src[j];
    v.x = f2tf(v.x); v.y = f2tf(v.y); v.z = f2tf(v.z); v.w = f2tf(v.w);
    dst[j] = v;
}

// ---------------- segment mean: fused count+scan (1 block), scatter, proto ----------------
__global__ void countscan_kernel(const int* __restrict__ labels) {
    __shared__ int cnt[N_CLS];
    __shared__ int b[1024];
    int t = threadIdx.x;   // 1024
    cnt[t] = 0; cnt[t + 1024] = 0;
    __syncthreads();
    for (int i = t; i < N_IMG; i += 1024) atomicAdd(&cnt[labels[i]], 1);
    __syncthreads();
    b[t] = cnt[2 * t] + cnt[2 * t + 1];
    __syncthreads();
    for (int off = 1; off < 1024; off <<= 1) {
        int v = (t >= off) ? b[t - off] : 0;
        __syncthreads();
        b[t] += v;
        __syncthreads();
    }
    int excl = (t == 0) ? 0 : b[t - 1];
    g_count[2 * t]      = cnt[2 * t];
    g_count[2 * t + 1]  = cnt[2 * t + 1];
    g_offset[2 * t]     = excl;
    g_offset[2 * t + 1] = excl + cnt[2 * t];
    g_cursor[2 * t]     = excl;
    g_cursor[2 * t + 1] = excl + cnt[2 * t];
}

__global__ void scatter_kernel(const int* __restrict__ labels) {
    int i = blockIdx.x * blockDim.x + threadIdx.x;
    if (i < N_IMG) {
        int l = labels[i];
        int pos = atomicAdd(&g_cursor[l], 1);
        g_perm[pos] = i;
    }
}

// grid (N_CLS, 2), 256 threads; 8-row unrolled gather, STREAMING loads
// (__ldcs = evict-first: the 512MB image stream must not pollute L2, which
//  keeps the attention chain's D-matrix/operands L2-resident during overlap)
__global__ void proto_kernel(const float* __restrict__ imgs) {
    int c = blockIdx.x;
    int col = blockIdx.y * 1024 + threadIdx.x * 4;
    int cnt  = g_count[c];
    int base = g_offset[c];
    float4 acc = make_float4(0.f, 0.f, 0.f, 0.f);
    int r = 0;
    for (; r + 8 <= cnt; r += 8) {
        float4 v[8];
#pragma unroll
        for (int u = 0; u < 8; u++) {
            int idx = g_perm[base + r + u];
            v[u] = __ldcs((const float4*)(imgs + (size_t)idx * IMG_D + col));
        }
#pragma unroll
        for (int u = 0; u < 8; u++) {
            acc.x += v[u].x; acc.y += v[u].y; acc.z += v[u].z; acc.w += v[u].w;
        }
    }
    for (; r < cnt; r++) {
        int idx = g_perm[base + r];
        float4 v0 = __ldcs((const float4*)(imgs + (size_t)idx * IMG_D + col));
        acc.x += v0.x; acc.y += v0.y; acc.z += v0.z; acc.w += v0.w;
    }
    float inv = (cnt > 0) ? (1.0f / (float)cnt) : 0.0f;
    acc.x *= inv; acc.y *= inv; acc.z *= inv; acc.w *= inv;
    *(float4*)(g_protos + (size_t)c * IMG_D + col) = acc;
}

// ---------------- TF32 tensor-core GEMM (cp.async, BK=32, pre-rounded operands) ----------------
__device__ __forceinline__ void mma_tf32(float* c, const unsigned* a, const unsigned* b) {
    asm volatile(
        "mma.sync.aligned.m16n8k8.row.col.f32.tf32.tf32.f32 "
        "{%0,%1,%2,%3}, {%4,%5,%6,%7}, {%8,%9}, {%0,%1,%2,%3};"
        : "+f"(c[0]), "+f"(c[1]), "+f"(c[2]), "+f"(c[3])
        : "r"(a[0]), "r"(a[1]), "r"(a[2]), "r"(a[3]), "r"(b[0]), "r"(b[1]));
}

__device__ __forceinline__ void cp16(unsigned dst, const float* src) {
    asm volatile("cp.async.cg.shared.global [%0], [%1], 16;" :: "r"(dst), "l"(src));
}
__device__ __forceinline__ void cp_commit() {
    asm volatile("cp.async.commit_group;");
}
__device__ __forceinline__ void cp_wait1() {
    asm volatile("cp.async.wait_group 1;");
}

template <bool TB, int BN, int BK, bool SYM>
__global__ __launch_bounds__(256)
void gemm_tc(const float* __restrict__ A, const float* __restrict__ B0,
             const float* __restrict__ B1, float* __restrict__ C0, float* __restrict__ C1,
             int M, int N, int K, int rout0) {
    const int S = 3;
    const int NFRAG = BN / 16;
    const int SA  = BK + 4;
    const int SBT = BK + 4;
    const int SBN = BN + 4;
    const int ASZ = 128 * SA;
    const int BSZ = TB ? BN * SBT : BK * SBN;

    const float* B = (blockIdx.z == 0) ? B0 : B1;
    float* C       = (blockIdx.z == 0) ? C0 : C1;
    bool rout      = (blockIdx.z == 0) && (rout0 != 0);

    extern __shared__ float sm[];
    float* As = sm;
    float* Bs = sm + S * ASZ;
    unsigned asu = (unsigned)__cvta_generic_to_shared(As);
    unsigned bsu = (unsigned)__cvta_generic_to_shared(Bs);

    int t = threadIdx.x;
    int warp = t >> 5, lane = t & 31, g = lane >> 2, tig = lane & 3;

    int bm, bn;
    if (SYM) {
        int bi = blockIdx.x, r = 0, rowlen = N / 128;
        while (bi >= rowlen) { bi -= rowlen; r++; rowlen--; }
        bm = r * 128;
        bn = (r + bi) * 128;
    } else {
        bm = blockIdx.y * 128;
        bn = blockIdx.x * BN;
    }
    int wm = (warp >> 1) * 32, wn = (warp & 1) * (BN / 2);

    float c[2][NFRAG][4];
#pragma unroll
    for (int mi = 0; mi < 2; mi++)
#pragma unroll
        for (int ni = 0; ni < NFRAG; ni++)
#pragma unroll
            for (int q = 0; q < 4; q++) c[mi][ni][q] = 0.f;

    auto load_stage = [&](int stg, int kt) {
        const int KC = BK / 4;
#pragma unroll
        for (int ch = t; ch < 32 * BK; ch += 256) {
            int row = ch / KC;
            int kq = (ch % KC) * 4;
            cp16(asu + (stg * ASZ + row * SA + kq) * 4, A + (size_t)(bm + row) * K + kt + kq);
        }
        if (TB) {
#pragma unroll
            for (int ch = t; ch < (BN * BK) / 4; ch += 256) {
                int row = ch / KC;
                int kq = (ch % KC) * 4;
                cp16(bsu + (stg * BSZ + row * SBT + kq) * 4, B + (size_t)(bn + row) * K + kt + kq);
            }
        } else {
            const int NC = BN / 4;
#pragma unroll
            for (int ch = t; ch < (BK * BN) / 4; ch += 256) {
                int krow = ch / NC;
                int nq = (ch % NC) * 4;
                cp16(bsu + (stg * BSZ + krow * SBN + nq) * 4, B + (size_t)(kt + krow) * N + bn + nq);
            }
        }
        cp_commit();
    };

    int T = K / BK;
    load_stage(0, 0);
    load_stage(1, BK);

    for (int kt = 0; kt < T; kt++) {
        cp_wait1();
        __syncthreads();
        int stg = kt % S;
        if (kt + S - 1 < T) load_stage((kt + S - 1) % S, (kt + S - 1) * BK);

        const float* Ast = As + stg * ASZ;
        const float* Bst = Bs + stg * BSZ;
#pragma unroll
        for (int ks = 0; ks < BK; ks += 8) {
            unsigned a[2][4], bf[NFRAG][2];
#pragma unroll
            for (int mi = 0; mi < 2; mi++) {
                int rb = wm + mi * 16;
                a[mi][0] = __float_as_uint(Ast[(rb + g) * SA + ks + tig]);
                a[mi][1] = __float_as_uint(Ast[(rb + g + 8) * SA + ks + tig]);
                a[mi][2] = __float_as_uint(Ast[(rb + g) * SA + ks + tig + 4]);
                a[mi][3] = __float_as_uint(Ast[(rb + g + 8) * SA + ks + tig + 4]);
            }
#pragma unroll
            for (int ni = 0; ni < NFRAG; ni++) {
                int cb = wn + ni * 8 + g;
                if (TB) {
                    bf[ni][0] = __float_as_uint(Bst[cb * SBT + ks + tig]);
                    bf[ni][1] = __float_as_uint(Bst[cb * SBT + ks + tig + 4]);
                } else {
                    bf[ni][0] = __float_as_uint(Bst[(ks + tig) * SBN + cb]);
                    bf[ni][1] = __float_as_uint(Bst[(ks + tig + 4) * SBN + cb]);
                }
            }
#pragma unroll
            for (int mi = 0; mi < 2; mi++)
#pragma unroll
                for (int ni = 0; ni < NFRAG; ni++)
                    mma_tf32(c[mi][ni], a[mi], bf[ni]);
        }
    }

#pragma unroll
    for (int mi = 0; mi < 2; mi++) {
#pragma unroll
        for (int ni = 0; ni < NFRAG; ni++) {
            int row = bm + wm + mi * 16 + g;
            int col = bn + wn + ni * 8 + tig * 2;
            float v0 = c[mi][ni][0], v1 = c[mi][ni][1];
            float v2 = c[mi][ni][2], v3 = c[mi][ni][3];
            if (rout) { v0 = f2tf(v0); v1 = f2tf(v1); v2 = f2tf(v2); v3 = f2tf(v3); }
            *(float2*)(C + (size_t)row * N + col)       = make_float2(v0, v1);
            *(float2*)(C + (size_t)(row + 8) * N + col) = make_float2(v2, v3);
            if (SYM && bm != bn) {
                C[(size_t)col * N + row]           = v0;
                C[(size_t)(col + 1) * N + row]     = v1;
                C[(size_t)col * N + row + 8]       = v2;
                C[(size_t)(col + 1) * N + row + 8] = v3;
            }
            if (SYM && bm == bn) {
                if (row == col)         g_rnorm[row]     = rsqrtf(fmaxf(v0, 1e-16f));
                if (row == col + 1)     g_rnorm[row]     = rsqrtf(fmaxf(v1, 1e-16f));
                if (row + 8 == col)     g_rnorm[row + 8] = rsqrtf(fmaxf(v2, 1e-16f));
                if (row + 8 == col + 1) g_rnorm[row + 8] = rsqrtf(fmaxf(v3, 1e-16f));
            }
        }
    }
}

#define SMEM_NT  (3 * (128 * 36 + 128 * 36) * 4)          // 110592
#define SMEM_NN  (3 * (128 * 36 + 32 * 68) * 4)           // 81408

// ---------------- shared softmax-selection machinery ----------------
__device__ __forceinline__ void sel_compute(const float* __restrict__ Dm,
                                            const float* __restrict__ rn,
                                            int i, int t, float* v,
                                            float* sred, int* sscan,
                                            int& cnt_out, int& base_out, float& m_out) {
    const float* row = Dm + (size_t)i * N_CLS;
    float rni = rn[i];
#pragma unroll
    for (int q = 0; q < 8; q++) {
        int j = t + q * 256;
        v[q] = row[j] * rni * rn[j];
    }
    float lmax = -1e30f;
    int lcnt = 0;
#pragma unroll
    for (int q = 0; q < 8; q++) {
        if (v[q] > THRESH) { lmax = fmaxf(lmax, v[q]); lcnt++; }
    }
    sred[t] = lmax;
    sscan[t] = lcnt;
    __syncthreads();
    for (int w = 128; w > 0; w >>= 1) {
        if (t < w) sred[t] = fmaxf(sred[t], sred[t + w]);
        __syncthreads();
    }
    float m = sred[0];
    __syncthreads();
    for (int off = 1; off < 256; off <<= 1) {
        int val = (t >= off) ? sscan[t - off] : 0;
        __syncthreads();
        sscan[t] += val;
        __syncthreads();
    }
    cnt_out = sscan[255];
    base_out = sscan[t] - lcnt;
    m_out = m;
}

__device__ __forceinline__ float sel_invS(int t, float* sred, const float* v, float m, int cnt) {
    float lsum = 0.f;
    if (cnt > 0) {
#pragma unroll
        for (int q = 0; q < 8; q++) {
            if (v[q] > THRESH) lsum += expf((v[q] - m) * TSOFT);
        }
    }
    __syncthreads();
    sred[t] = lsum;
    __syncthreads();
    for (int w = 128; w > 0; w >>= 1) {
        if (t < w) sred[t] += sred[t + w];
        __syncthreads();
    }
    return (cnt > 0) ? (1.0f / sred[0]) : 0.f;
}

// ---------------- fused cosine-scale + masked softmax + sparse matmul (exact) ----------------
__global__ __launch_bounds__(256)
void softmax_spmm_kernel(const float* __restrict__ Dm, const float* __restrict__ rn,
                         const float* __restrict__ V, const int* __restrict__ map,
                         float* __restrict__ out, int vd, int round_out) {
    __shared__ float sred[256];
    __shared__ int   sscan[256];
    __shared__ int   sel_idx[N_CLS];
    __shared__ float sel_w[N_CLS];

    int i = blockIdx.x;
    int t = threadIdx.x;
    float v[8];
    int cnt, base; float m;
    sel_compute(Dm, rn, i, t, v, sred, sscan, cnt, base, m);

    float acc[8];
#pragma unroll
    for (int q = 0; q < 8; q++) acc[q] = 0.f;
    int nq = vd >> 8;

    if (cnt > 0) {
        float invS = sel_invS(t, sred, v, m, cnt);
        int pos = base;
#pragma unroll
        for (int q = 0; q < 8; q++) {
            if (v[q] > THRESH) {
                sel_idx[pos] = t + q * 256;
                sel_w[pos] = expf((v[q] - m) * TSOFT) * invS;
                pos++;
            }
        }
        __syncthreads();
        for (int s = 0; s < cnt; s++) {
            int j = sel_idx[s];
            float w = sel_w[s];
            int src = map ? map[j] : j;
            const float* vr = V + (size_t)src * vd;
#pragma unroll
            for (int q = 0; q < 8; q++)
                if (q < nq) acc[q] += w * vr[t + q * 256];
        }
    } else {
        float w = 1.0f / (float)N_CLS;
        for (int j = 0; j < N_CLS; j++) {
            int src = map ? map[j] : j;
            const float* vr = V + (size_t)src * vd;
#pragma unroll
            for (int q = 0; q < 8; q++)
                if (q < nq) acc[q] += w * vr[t + q * 256];
        }
    }

#pragma unroll
    for (int q = 0; q < 8; q++)
        if (q < nq) {
            float o = acc[q];
            if (round_out) o = f2tf(o);
            out[(size_t)i * vd + t + q * 256] = o;
        }
}

// ---------------- phase 1: selection weights only (runs concurrent with proto) ----------------
__global__ __launch_bounds__(256)
void sel_weights_kernel(const float* __restrict__ Dm, const float* __restrict__ rn) {
    __shared__ float sred[256];
    __shared__ int   sscan[256];
    int i = blockIdx.x;
    int t = threadIdx.x;
    float v[8];
    int cnt, base; float m;
    sel_compute(Dm, rn, i, t, v, sred, sscan, cnt, base, m);
    if (t == 0) g_sel_cnt[i] = cnt;
    if (cnt > 0 && cnt <= MAXSEL) {
        float invS = sel_invS(t, sred, v, m, cnt);
        int pos = base;
#pragma unroll
        for (int q = 0; q < 8; q++) {
            if (v[q] > THRESH) {
                g_sel_idx[i * MAXSEL + pos] = t + q * 256;
                g_sel_w[i * MAXSEL + pos]   = expf((v[q] - m) * TSOFT) * invS;
                pos++;
            }
        }
    }
}

// ---------------- phase 2: sparse gather of protos (post-join tail) ----------------
__global__ __launch_bounds__(256)
void sel_gather_kernel(const float* __restrict__ Dm, const float* __restrict__ rn,
                       const float* __restrict__ V, const int* __restrict__ map,
                       float* __restrict__ out, int vd) {
    int i = blockIdx.x;
    int t = threadIdx.x;
    int cnt = g_sel_cnt[i];
    float acc[8];
#pragma unroll
    for (int q = 0; q < 8; q++) acc[q] = 0.f;
    int nq = vd >> 8;

    if (cnt > 0 && cnt <= MAXSEL) {
        for (int s = 0; s < cnt; s++) {
            int j = g_sel_idx[i * MAXSEL + s];
            float w = g_sel_w[i * MAXSEL + s];
            int src = map ? map[j] : j;
            const float* vr = V + (size_t)src * vd;
#pragma unroll
            for (int q = 0; q < 8; q++)
                if (q < nq) acc[q] += w * vr[t + q * 256];
        }
    } else if (cnt == 0) {
        float w = 1.0f / (float)N_CLS;
        for (int j = 0; j < N_CLS; j++) {
            int src = map ? map[j] : j;
            const float* vr = V + (size_t)src * vd;
#pragma unroll
            for (int q = 0; q < 8; q++)
                if (q < nq) acc[q] += w * vr[t + q * 256];
        }
    } else {
        __shared__ float sred[256];
        __shared__ int   sscan[256];
        __shared__ int   sel_idx[N_CLS];
        __shared__ float sel_w[N_CLS];
        float v[8];
        int c2, base; float m;
        sel_compute(Dm, rn, i, t, v, sred, sscan, c2, base, m);
        float invS = sel_invS(t, sred, v, m, c2);
        int pos = base;
#pragma unroll
        for (int q = 0; q < 8; q++) {
            if (v[q] > THRESH) {
                sel_idx[pos] = t + q * 256;
                sel_w[pos] = expf((v[q] - m) * TSOFT) * invS;
                pos++;
            }
        }
        __syncthreads();
        for (int s = 0; s < c2; s++) {
            int j = sel_idx[s];
            float w = sel_w[s];
            int src = map ? map[j] : j;
            const float* vr = V + (size_t)src * vd;
#pragma unroll
            for (int q = 0; q < 8; q++)
                if (q < nq) acc[q] += w * vr[t + q * 256];
        }
    }

#pragma unroll
    for (int q = 0; q < 8; q++)
        if (q < nq) out[(size_t)i * vd + t + q * 256] = acc[q];
}

// ---------------- launch ----------------
extern "C" void kernel_launch(void* const* d_in, const int* in_sizes, int n_in,
                              void* d_out, int out_size) {
    const float* image      = (const float*)d_in[0];
    const float* attributes = (const float*)d_in[1];
    const int*   labels     = (const int*)d_in[2];
    const int*   tpl        = (const int*)d_in[3];
    const float* ga         = (const float*)d_in[4];
    const float* gv         = (const float*)d_in[5];
    float* out = (float*)d_out;

    float *a1p, *a2p, *b2p, *dp, *rnp, *prp, *attrp, *gap, *gvp;
    cudaGetSymbolAddress((void**)&a1p, g_a1);
    cudaGetSymbolAddress((void**)&a2p, g_a2);
    cudaGetSymbolAddress((void**)&b2p, g_b2);
    cudaGetSymbolAddress((void**)&dp, g_d);
    cudaGetSymbolAddress((void**)&rnp, g_rnorm);
    cudaGetSymbolAddress((void**)&prp, g_protos);
    cudaGetSymbolAddress((void**)&attrp, g_attr_tf);
    cudaGetSymbolAddress((void**)&gap, g_ga_tf);
    cudaGetSymbolAddress((void**)&gvp, g_gv_tf);

    static cudaStream_t s_proto = nullptr;
    static cudaEvent_t ev_fork = nullptr, ev_proto = nullptr;
    if (!s_proto) {
        cudaStreamCreateWithFlags(&s_proto, cudaStreamNonBlocking);
        cudaEventCreateWithFlags(&ev_fork, cudaEventDisableTiming);
        cudaEventCreateWithFlags(&ev_proto, cudaEventDisableTiming);
        cudaFuncSetAttribute(gemm_tc<true, 128, 32, true>,
                             cudaFuncAttributeMaxDynamicSharedMemorySize, SMEM_NT);
        cudaFuncSetAttribute(gemm_tc<false, 64, 32, false>,
                             cudaFuncAttributeMaxDynamicSharedMemorySize, SMEM_NN);
    }

    const int NTRI = (N_CLS / 128) * (N_CLS / 128 + 1) / 2;  // 136

    // ---- fork proto chain ----
    cudaEventRecord(ev_fork, 0);
    cudaStreamWaitEvent(s_proto, ev_fork, 0);

    countscan_kernel<<<1, 1024, 0, s_proto>>>(labels);
    scatter_kernel<<<N_IMG / 256, 256, 0, s_proto>>>(labels);
    proto_kernel<<<dim3(N_CLS, 2), 256, 0, s_proto>>>(image);
    cudaEventRecord(ev_proto, s_proto);

    // ---- attention critical path (main stream) ----
    round_all_kernel<<<(A4 + 2 * G4 + 255) / 256, 256>>>(attributes, ga, gv);

    gemm_tc<false, 64, 32, false><<<dim3(HC / 64, N_CLS / 128, 2), 256, SMEM_NN>>>(
        attrp, gap, gvp, a1p, b2p, N_CLS, HC, ATT_D, 1);

    gemm_tc<true, 128, 32, true><<<NTRI, 256, SMEM_NT>>>(
        a1p, a1p, nullptr, dp, nullptr, N_CLS, N_CLS, HC, 0);

    softmax_spmm_kernel<<<N_CLS, 256>>>(dp, rnp, b2p, nullptr, a2p, HC, 1);

    gemm_tc<true, 128, 32, true><<<NTRI, 256, SMEM_NT>>>(
        a2p, a2p, nullptr, dp, nullptr, N_CLS, N_CLS, HC, 0);

    // phase 1: weights — runs while proto is still streaming HBM
    sel_weights_kernel<<<N_CLS, 256>>>(dp, rnp);

    // join proto; phase 2: tiny gather tail
    cudaStreamWaitEvent(0, ev_proto, 0);
    sel_gather_kernel<<<N_CLS, 256>>>(dp, rnp, prp, tpl, out, IMG_D);
}

// round 14
// speedup vs baseline: 1.0108x; 1.0108x over previous
#include <cuda_runtime.h>
#include <math.h>

#define N_IMG   65536
#define IMG_D   2048
#define N_CLS   2048
#define ATT_D   1024
#define HC      512
#define TSOFT   10.0f
#define THRESH  0.17364817766693041f
#define MAXSEL  128
#define PROTO_GRID 296   // 2 blocks/SM on 148 SMs: caps occupancy footprint

// ---------------- scratch (static device memory; no allocation) ----------------
__device__ float g_a1[N_CLS * HC];
__device__ float g_a2[N_CLS * HC];
__device__ float g_b2[N_CLS * HC];
__device__ float g_d[N_CLS * N_CLS];
__device__ float g_rnorm[N_CLS];
__device__ float g_protos[N_CLS * IMG_D];
__device__ float g_attr_tf[N_CLS * ATT_D];
__device__ float g_ga_tf[ATT_D * HC];
__device__ float g_gv_tf[ATT_D * HC];
__device__ int   g_count[N_CLS];
__device__ int   g_offset[N_CLS];
__device__ int   g_cursor[N_CLS];
__device__ int   g_perm[N_IMG];
__device__ int   g_sel_cnt[N_CLS];
__device__ int   g_sel_idx[N_CLS * MAXSEL];
__device__ float g_sel_w[N_CLS * MAXSEL];

__device__ __forceinline__ float f2tf(float x) {
    unsigned r;
    asm("cvt.rna.tf32.f32 %0, %1;" : "=r"(r) : "f"(x));
    return __uint_as_float(r);
}

// round attr+ga+gv to tf32 in one launch (flat float4 index)
#define A4  (N_CLS * ATT_D / 4)
#define G4  (ATT_D * HC / 4)
__global__ void round_all_kernel(const float* __restrict__ attr, const float* __restrict__ ga,
                                 const float* __restrict__ gv) {
    int i = blockIdx.x * blockDim.x + threadIdx.x;
    const float4* src;
    float4* dst;
    int j;
    if (i < A4)            { src = (const float4*)attr; dst = (float4*)g_attr_tf; j = i; }
    else if (i < A4 + G4)  { src = (const float4*)ga;   dst = (float4*)g_ga_tf;   j = i - A4; }
    else if (i < A4 + 2*G4){ src = (const float4*)gv;   dst = (float4*)g_gv_tf;   j = i - A4 - G4; }
    else return;
    float4 v = src[j];
    v.x = f2tf(v.x); v.y = f2tf(v.y); v.z = f2tf(v.z); v.w = f2tf(v.w);
    dst[j] = v;
}

// ---------------- segment mean: fused count+scan (1 block), scatter, proto ----------------
__global__ void countscan_kernel(const int* __restrict__ labels) {
    __shared__ int cnt[N_CLS];
    __shared__ int b[1024];
    int t = threadIdx.x;   // 1024
    cnt[t] = 0; cnt[t + 1024] = 0;
    __syncthreads();
    for (int i = t; i < N_IMG; i += 1024) atomicAdd(&cnt[labels[i]], 1);
    __syncthreads();
    b[t] = cnt[2 * t] + cnt[2 * t + 1];
    __syncthreads();
    for (int off = 1; off < 1024; off <<= 1) {
        int v = (t >= off) ? b[t - off] : 0;
        __syncthreads();
        b[t] += v;
        __syncthreads();
    }
    int excl = (t == 0) ? 0 : b[t - 1];
    g_count[2 * t]      = cnt[2 * t];
    g_count[2 * t + 1]  = cnt[2 * t + 1];
    g_offset[2 * t]     = excl;
    g_offset[2 * t + 1] = excl + cnt[2 * t];
    g_cursor[2 * t]     = excl;
    g_cursor[2 * t + 1] = excl + cnt[2 * t];
}

__global__ void scatter_kernel(const int* __restrict__ labels) {
    int i = blockIdx.x * blockDim.x + threadIdx.x;
    if (i < N_IMG) {
        int l = labels[i];
        int pos = atomicAdd(&g_cursor[l], 1);
        g_perm[pos] = i;
    }
}

// persistent-style proto: grid-stride over 4096 (class, half) work items.
// Caps resident blocks to PROTO_GRID (2/SM) so the attention chain's GEMM
// blocks get SM slots during overlap; in-flight loads (296*256*8*16B ~ 9.7MB)
// still far exceed the BW-delay product (~2.2MB), so DRAM stays saturated.
// Per-class accumulation order identical to before -> bit-identical output.
__global__ void proto_kernel(const float* __restrict__ imgs) {
    for (int w = blockIdx.x; w < N_CLS * 2; w += PROTO_GRID) {
        int c = w >> 1;
        int col = (w & 1) * 1024 + threadIdx.x * 4;
        int cnt  = g_count[c];
        int base = g_offset[c];
        float4 acc = make_float4(0.f, 0.f, 0.f, 0.f);
        int r = 0;
        for (; r + 8 <= cnt; r += 8) {
            float4 v[8];
#pragma unroll
            for (int u = 0; u < 8; u++) {
                int idx = g_perm[base + r + u];
                v[u] = __ldcs((const float4*)(imgs + (size_t)idx * IMG_D + col));
            }
#pragma unroll
            for (int u = 0; u < 8; u++) {
                acc.x += v[u].x; acc.y += v[u].y; acc.z += v[u].z; acc.w += v[u].w;
            }
        }
        for (; r < cnt; r++) {
            int idx = g_perm[base + r];
            float4 v0 = __ldcs((const float4*)(imgs + (size_t)idx * IMG_D + col));
            acc.x += v0.x; acc.y += v0.y; acc.z += v0.z; acc.w += v0.w;
        }
        float inv = (cnt > 0) ? (1.0f / (float)cnt) : 0.0f;
        acc.x *= inv; acc.y *= inv; acc.z *= inv; acc.w *= inv;
        *(float4*)(g_protos + (size_t)c * IMG_D + col) = acc;
    }
}

// ---------------- TF32 tensor-core GEMM (cp.async, BK=32, pre-rounded operands) ----------------
__device__ __forceinline__ void mma_tf32(float* c, const unsigned* a, const unsigned* b) {
    asm volatile(
        "mma.sync.aligned.m16n8k8.row.col.f32.tf32.tf32.f32 "
        "{%0,%1,%2,%3}, {%4,%5,%6,%7}, {%8,%9}, {%0,%1,%2,%3};"
        : "+f"(c[0]), "+f"(c[1]), "+f"(c[2]), "+f"(c[3])
        : "r"(a[0]), "r"(a[1]), "r"(a[2]), "r"(a[3]), "r"(b[0]), "r"(b[1]));
}

__device__ __forceinline__ void cp16(unsigned dst, const float* src) {
    asm volatile("cp.async.cg.shared.global [%0], [%1], 16;" :: "r"(dst), "l"(src));
}
__device__ __forceinline__ void cp_commit() {
    asm volatile("cp.async.commit_group;");
}
__device__ __forceinline__ void cp_wait1() {
    asm volatile("cp.async.wait_group 1;");
}

template <bool TB, int BN, int BK, bool SYM>
__global__ __launch_bounds__(256)
void gemm_tc(const float* __restrict__ A, const float* __restrict__ B0,
             const float* __restrict__ B1, float* __restrict__ C0, float* __restrict__ C1,
             int M, int N, int K, int rout0) {
    const int S = 3;
    const int NFRAG = BN / 16;
    const int SA  = BK + 4;
    const int SBT = BK + 4;
    const int SBN = BN + 4;
    const int ASZ = 128 * SA;
    const int BSZ = TB ? BN * SBT : BK * SBN;

    const float* B = (blockIdx.z == 0) ? B0 : B1;
    float* C       = (blockIdx.z == 0) ? C0 : C1;
    bool rout      = (blockIdx.z == 0) && (rout0 != 0);

    extern __shared__ float sm[];
    float* As = sm;
    float* Bs = sm + S * ASZ;
    unsigned asu = (unsigned)__cvta_generic_to_shared(As);
    unsigned bsu = (unsigned)__cvta_generic_to_shared(Bs);

    int t = threadIdx.x;
    int warp = t >> 5, lane = t & 31, g = lane >> 2, tig = lane & 3;

    int bm, bn;
    if (SYM) {
        int bi = blockIdx.x, r = 0, rowlen = N / 128;
        while (bi >= rowlen) { bi -= rowlen; r++; rowlen--; }
        bm = r * 128;
        bn = (r + bi) * 128;
    } else {
        bm = blockIdx.y * 128;
        bn = blockIdx.x * BN;
    }
    int wm = (warp >> 1) * 32, wn = (warp & 1) * (BN / 2);

    float c[2][NFRAG][4];
#pragma unroll
    for (int mi = 0; mi < 2; mi++)
#pragma unroll
        for (int ni = 0; ni < NFRAG; ni++)
#pragma unroll
            for (int q = 0; q < 4; q++) c[mi][ni][q] = 0.f;

    auto load_stage = [&](int stg, int kt) {
        const int KC = BK / 4;
#pragma unroll
        for (int ch = t; ch < 32 * BK; ch += 256) {
            int row = ch / KC;
            int kq = (ch % KC) * 4;
            cp16(asu + (stg * ASZ + row * SA + kq) * 4, A + (size_t)(bm + row) * K + kt + kq);
        }
        if (TB) {
#pragma unroll
            for (int ch = t; ch < (BN * BK) / 4; ch += 256) {
                int row = ch / KC;
                int kq = (ch % KC) * 4;
                cp16(bsu + (stg * BSZ + row * SBT + kq) * 4, B + (size_t)(bn + row) * K + kt + kq);
            }
        } else {
            const int NC = BN / 4;
#pragma unroll
            for (int ch = t; ch < (BK * BN) / 4; ch += 256) {
                int krow = ch / NC;
                int nq = (ch % NC) * 4;
                cp16(bsu + (stg * BSZ + krow * SBN + nq) * 4, B + (size_t)(kt + krow) * N + bn + nq);
            }
        }
        cp_commit();
    };

    int T = K / BK;
    load_stage(0, 0);
    load_stage(1, BK);

    for (int kt = 0; kt < T; kt++) {
        cp_wait1();
        __syncthreads();
        int stg = kt % S;
        if (kt + S - 1 < T) load_stage((kt + S - 1) % S, (kt + S - 1) * BK);

        const float* Ast = As + stg * ASZ;
        const float* Bst = Bs + stg * BSZ;
#pragma unroll
        for (int ks = 0; ks < BK; ks += 8) {
            unsigned a[2][4], bf[NFRAG][2];
#pragma unroll
            for (int mi = 0; mi < 2; mi++) {
                int rb = wm + mi * 16;
                a[mi][0] = __float_as_uint(Ast[(rb + g) * SA + ks + tig]);
                a[mi][1] = __float_as_uint(Ast[(rb + g + 8) * SA + ks + tig]);
                a[mi][2] = __float_as_uint(Ast[(rb + g) * SA + ks + tig + 4]);
                a[mi][3] = __float_as_uint(Ast[(rb + g + 8) * SA + ks + tig + 4]);
            }
#pragma unroll
            for (int ni = 0; ni < NFRAG; ni++) {
                int cb = wn + ni * 8 + g;
                if (TB) {
                    bf[ni][0] = __float_as_uint(Bst[cb * SBT + ks + tig]);
                    bf[ni][1] = __float_as_uint(Bst[cb * SBT + ks + tig + 4]);
                } else {
                    bf[ni][0] = __float_as_uint(Bst[(ks + tig) * SBN + cb]);
                    bf[ni][1] = __float_as_uint(Bst[(ks + tig + 4) * SBN + cb]);
                }
            }
#pragma unroll
            for (int mi = 0; mi < 2; mi++)
#pragma unroll
                for (int ni = 0; ni < NFRAG; ni++)
                    mma_tf32(c[mi][ni], a[mi], bf[ni]);
        }
    }

#pragma unroll
    for (int mi = 0; mi < 2; mi++) {
#pragma unroll
        for (int ni = 0; ni < NFRAG; ni++) {
            int row = bm + wm + mi * 16 + g;
            int col = bn + wn + ni * 8 + tig * 2;
            float v0 = c[mi][ni][0], v1 = c[mi][ni][1];
            float v2 = c[mi][ni][2], v3 = c[mi][ni][3];
            if (rout) { v0 = f2tf(v0); v1 = f2tf(v1); v2 = f2tf(v2); v3 = f2tf(v3); }
            *(float2*)(C + (size_t)row * N + col)       = make_float2(v0, v1);
            *(float2*)(C + (size_t)(row + 8) * N + col) = make_float2(v2, v3);
            if (SYM && bm != bn) {
                C[(size_t)col * N + row]           = v0;
                C[(size_t)(col + 1) * N + row]     = v1;
                C[(size_t)col * N + row + 8]       = v2;
                C[(size_t)(col + 1) * N + row + 8] = v3;
            }
            if (SYM && bm == bn) {
                if (row == col)         g_rnorm[row]     = rsqrtf(fmaxf(v0, 1e-16f));
                if (row == col + 1)     g_rnorm[row]     = rsqrtf(fmaxf(v1, 1e-16f));
                if (row + 8 == col)     g_rnorm[row + 8] = rsqrtf(fmaxf(v2, 1e-16f));
                if (row + 8 == col + 1) g_rnorm[row + 8] = rsqrtf(fmaxf(v3, 1e-16f));
            }
        }
    }
}

#define SMEM_NT  (3 * (128 * 36 + 128 * 36) * 4)          // 110592
#define SMEM_NN  (3 * (128 * 36 + 32 * 68) * 4)           // 81408

// ---------------- shared softmax-selection machinery ----------------
__device__ __forceinline__ void sel_compute(const float* __restrict__ Dm,
                                            const float* __restrict__ rn,
                                            int i, int t, float* v,
                                            float* sred, int* sscan,
                                            int& cnt_out, int& base_out, float& m_out) {
    const float* row = Dm + (size_t)i * N_CLS;
    float rni = rn[i];
#pragma unroll
    for (int q = 0; q < 8; q++) {
        int j = t + q * 256;
        v[q] = row[j] * rni * rn[j];
    }
    float lmax = -1e30f;
    int lcnt = 0;
#pragma unroll
    for (int q = 0; q < 8; q++) {
        if (v[q] > THRESH) { lmax = fmaxf(lmax, v[q]); lcnt++; }
    }
    sred[t] = lmax;
    sscan[t] = lcnt;
    __syncthreads();
    for (int w = 128; w > 0; w >>= 1) {
        if (t < w) sred[t] = fmaxf(sred[t], sred[t + w]);
        __syncthreads();
    }
    float m = sred[0];
    __syncthreads();
    for (int off = 1; off < 256; off <<= 1) {
        int val = (t >= off) ? sscan[t - off] : 0;
        __syncthreads();
        sscan[t] += val;
        __syncthreads();
    }
    cnt_out = sscan[255];
    base_out = sscan[t] - lcnt;
    m_out = m;
}

__device__ __forceinline__ float sel_invS(int t, float* sred, const float* v, float m, int cnt) {
    float lsum = 0.f;
    if (cnt > 0) {
#pragma unroll
        for (int q = 0; q < 8; q++) {
            if (v[q] > THRESH) lsum += expf((v[q] - m) * TSOFT);
        }
    }
    __syncthreads();
    sred[t] = lsum;
    __syncthreads();
    for (int w = 128; w > 0; w >>= 1) {
        if (t < w) sred[t] += sred[t + w];
        __syncthreads();
    }
    return (cnt > 0) ? (1.0f / sred[0]) : 0.f;
}

// ---------------- fused cosine-scale + masked softmax + sparse matmul (exact) ----------------
__global__ __launch_bounds__(256)
void softmax_spmm_kernel(const float* __restrict__ Dm, const float* __restrict__ rn,
                         const float* __restrict__ V, const int* __restrict__ map,
                         float* __restrict__ out, int vd, int round_out) {
    __shared__ float sred[256];
    __shared__ int   sscan[256];
    __shared__ int   sel_idx[N_CLS];
    __shared__ float sel_w[N_CLS];

    int i = blockIdx.x;
    int t = threadIdx.x;
    float v[8];
    int cnt, base; float m;
    sel_compute(Dm, rn, i, t, v, sred, sscan, cnt, base, m);

    float acc[8];
#pragma unroll
    for (int q = 0; q < 8; q++) acc[q] = 0.f;
    int nq = vd >> 8;

    if (cnt > 0) {
        float invS = sel_invS(t, sred, v, m, cnt);
        int pos = base;
#pragma unroll
        for (int q = 0; q < 8; q++) {
            if (v[q] > THRESH) {
                sel_idx[pos] = t + q * 256;
                sel_w[pos] = expf((v[q] - m) * TSOFT) * invS;
                pos++;
            }
        }
        __syncthreads();
        for (int s = 0; s < cnt; s++) {
            int j = sel_idx[s];
            float w = sel_w[s];
            int src = map ? map[j] : j;
            const float* vr = V + (size_t)src * vd;
#pragma unroll
            for (int q = 0; q < 8; q++)
                if (q < nq) acc[q] += w * vr[t + q * 256];
        }
    } else {
        float w = 1.0f / (float)N_CLS;
        for (int j = 0; j < N_CLS; j++) {
            int src = map ? map[j] : j;
            const float* vr = V + (size_t)src * vd;
#pragma unroll
            for (int q = 0; q < 8; q++)
                if (q < nq) acc[q] += w * vr[t + q * 256];
        }
    }

#pragma unroll
    for (int q = 0; q < 8; q++)
        if (q < nq) {
            float o = acc[q];
            if (round_out) o = f2tf(o);
            out[(size_t)i * vd + t + q * 256] = o;
        }
}

// ---------------- phase 1: selection weights only (runs concurrent with proto) ----------------
__global__ __launch_bounds__(256)
void sel_weights_kernel(const float* __restrict__ Dm, const float* __restrict__ rn) {
    __shared__ float sred[256];
    __shared__ int   sscan[256];
    int i = blockIdx.x;
    int t = threadIdx.x;
    float v[8];
    int cnt, base; float m;
    sel_compute(Dm, rn, i, t, v, sred, sscan, cnt, base, m);
    if (t == 0) g_sel_cnt[i] = cnt;
    if (cnt > 0 && cnt <= MAXSEL) {
        float invS = sel_invS(t, sred, v, m, cnt);
        int pos = base;
#pragma unroll
        for (int q = 0; q < 8; q++) {
            if (v[q] > THRESH) {
                g_sel_idx[i * MAXSEL + pos] = t + q * 256;
                g_sel_w[i * MAXSEL + pos]   = expf((v[q] - m) * TSOFT) * invS;
                pos++;
            }
        }
    }
}

// ---------------- phase 2: sparse gather of protos (post-join tail) ----------------
__global__ __launch_bounds__(256)
void sel_gather_kernel(const float* __restrict__ Dm, const float* __restrict__ rn,
                       const float* __restrict__ V, const int* __restrict__ map,
                       float* __restrict__ out, int vd) {
    int i = blockIdx.x;
    int t = threadIdx.x;
    int cnt = g_sel_cnt[i];
    float acc[8];
#pragma unroll
    for (int q = 0; q < 8; q++) acc[q] = 0.f;
    int nq = vd >> 8;

    if (cnt > 0 && cnt <= MAXSEL) {
        for (int s = 0; s < cnt; s++) {
            int j = g_sel_idx[i * MAXSEL + s];
            float w = g_sel_w[i * MAXSEL + s];
            int src = map ? map[j] : j;
            const float* vr = V + (size_t)src * vd;
#pragma unroll
            for (int q = 0; q < 8; q++)
                if (q < nq) acc[q] += w * vr[t + q * 256];
        }
    } else if (cnt == 0) {
        float w = 1.0f / (float)N_CLS;
        for (int j = 0; j < N_CLS; j++) {
            int src = map ? map[j] : j;
            const float* vr = V + (size_t)src * vd;
#pragma unroll
            for (int q = 0; q < 8; q++)
                if (q < nq) acc[q] += w * vr[t + q * 256];
        }
    } else {
        __shared__ float sred[256];
        __shared__ int   sscan[256];
        __shared__ int   sel_idx[N_CLS];
        __shared__ float sel_w[N_CLS];
        float v[8];
        int c2, base; float m;
        sel_compute(Dm, rn, i, t, v, sred, sscan, c2, base, m);
        float invS = sel_invS(t, sred, v, m, c2);
        int pos = base;
#pragma unroll
        for (int q = 0; q < 8; q++) {
            if (v[q] > THRESH) {
                sel_idx[pos] = t + q * 256;
                sel_w[pos] = expf((v[q] - m) * TSOFT) * invS;
                pos++;
            }
        }
        __syncthreads();
        for (int s = 0; s < c2; s++) {
            int j = sel_idx[s];
            float w = sel_w[s];
            int src = map ? map[j] : j;
            const float* vr = V + (size_t)src * vd;
#pragma unroll
            for (int q = 0; q < 8; q++)
                if (q < nq) acc[q] += w * vr[t + q * 256];
        }
    }

#pragma unroll
    for (int q = 0; q < 8; q++)
        if (q < nq) out[(size_t)i * vd + t + q * 256] = acc[q];
}

// ---------------- launch ----------------
extern "C" void kernel_launch(void* const* d_in, const int* in_sizes, int n_in,
                              void* d_out, int out_size) {
    const float* image      = (const float*)d_in[0];
    const float* attributes = (const float*)d_in[1];
    const int*   labels     = (const int*)d_in[2];
    const int*   tpl        = (const int*)d_in[3];
    const float* ga         = (const float*)d_in[4];
    const float* gv         = (const float*)d_in[5];
    float* out = (float*)d_out;

    float *a1p, *a2p, *b2p, *dp, *rnp, *prp, *attrp, *gap, *gvp;
    cudaGetSymbolAddress((void**)&a1p, g_a1);
    cudaGetSymbolAddress((void**)&a2p, g_a2);
    cudaGetSymbolAddress((void**)&b2p, g_b2);
    cudaGetSymbolAddress((void**)&dp, g_d);
    cudaGetSymbolAddress((void**)&rnp, g_rnorm);
    cudaGetSymbolAddress((void**)&prp, g_protos);
    cudaGetSymbolAddress((void**)&attrp, g_attr_tf);
    cudaGetSymbolAddress((void**)&gap, g_ga_tf);
    cudaGetSymbolAddress((void**)&gvp, g_gv_tf);

    static cudaStream_t s_proto = nullptr;
    static cudaEvent_t ev_fork = nullptr, ev_proto = nullptr;
    if (!s_proto) {
        cudaStreamCreateWithFlags(&s_proto, cudaStreamNonBlocking);
        cudaEventCreateWithFlags(&ev_fork, cudaEventDisableTiming);
        cudaEventCreateWithFlags(&ev_proto, cudaEventDisableTiming);
        cudaFuncSetAttribute(gemm_tc<true, 128, 32, true>,
                             cudaFuncAttributeMaxDynamicSharedMemorySize, SMEM_NT);
        cudaFuncSetAttribute(gemm_tc<false, 64, 32, false>,
                             cudaFuncAttributeMaxDynamicSharedMemorySize, SMEM_NN);
    }

    const int NTRI = (N_CLS / 128) * (N_CLS / 128 + 1) / 2;  // 136

    // ---- fork proto chain ----
    cudaEventRecord(ev_fork, 0);
    cudaStreamWaitEvent(s_proto, ev_fork, 0);

    countscan_kernel<<<1, 1024, 0, s_proto>>>(labels);
    scatter_kernel<<<N_IMG / 256, 256, 0, s_proto>>>(labels);
    proto_kernel<<<PROTO_GRID, 256, 0, s_proto>>>(image);
    cudaEventRecord(ev_proto, s_proto);

    // ---- attention critical path (main stream) ----
    round_all_kernel<<<(A4 + 2 * G4 + 255) / 256, 256>>>(attributes, ga, gv);

    gemm_tc<false, 64, 32, false><<<dim3(HC / 64, N_CLS / 128, 2), 256, SMEM_NN>>>(
        attrp, gap, gvp, a1p, b2p, N_CLS, HC, ATT_D, 1);

    gemm_tc<true, 128, 32, true><<<NTRI, 256, SMEM_NT>>>(
        a1p, a1p, nullptr, dp, nullptr, N_CLS, N_CLS, HC, 0);

    softmax_spmm_kernel<<<N_CLS, 256>>>(dp, rnp, b2p, nullptr, a2p, HC, 1);

    gemm_tc<true, 128, 32, true><<<NTRI, 256, SMEM_NT>>>(
        a2p, a2p, nullptr, dp, nullptr, N_CLS, N_CLS, HC, 0);

    // phase 1: weights — runs while proto is still streaming HBM
    sel_weights_kernel<<<N_CLS, 256>>>(dp, rnp);

    // join proto; phase 2: tiny gather tail
    cudaStreamWaitEvent(0, ev_proto, 0);
    sel_gather_kernel<<<N_CLS, 256>>>(dp, rnp, prp, tpl, out, IMG_D);
}